// round 10
// baseline (speedup 1.0000x reference)
#include <cuda_runtime.h>
#include <cstdint>

#define DIM   1024
#define SEQ   2048
#define NBATCH 2
#define MTOT  (NBATCH*SEQ)   /* 4096 */
#define VOCAB 32000

// ---------------- scratch (device globals; no allocations allowed) ----------
__device__ __align__(16) float g_h [MTOT*DIM];
__device__ __align__(16) float g_q [MTOT*DIM];
__device__ __align__(16) float g_k [MTOT*DIM];
__device__ __align__(16) float g_v [MTOT*DIM];
__device__ __align__(16) float g_sc[(size_t)NBATCH*SEQ*SEQ];   // scores / attn
__device__ __align__(16) float g_ao[MTOT*DIM];

// ---------------- helpers ---------------------------------------------------
__device__ __forceinline__ uint32_t f2tf(float x) {
    uint32_t r;
    asm("cvt.rna.tf32.f32 %0, %1;" : "=r"(r) : "f"(x));
    return r;
}

__device__ __forceinline__ void mma8(float* c, const uint32_t* a, const uint32_t* b) {
    asm volatile(
        "mma.sync.aligned.m16n8k8.row.col.f32.tf32.tf32.f32 "
        "{%0,%1,%2,%3},{%4,%5,%6,%7},{%8,%9},{%0,%1,%2,%3};"
        : "+f"(c[0]), "+f"(c[1]), "+f"(c[2]), "+f"(c[3])
        : "r"(a[0]), "r"(a[1]), "r"(a[2]), "r"(a[3]), "r"(b[0]), "r"(b[1]));
}

// ---------------- embedding: h = tok_emb[x] + pos_emb -----------------------
__global__ void embed_kernel(const int* __restrict__ x,
                             const float* __restrict__ tok,
                             const float* __restrict__ pos) {
    const int r  = blockIdx.x;          // 0..4095
    const int s  = r & (SEQ - 1);
    const int d4 = threadIdx.x * 4;
    const int t  = x[r];
    float4 a = *(const float4*)(tok + (long)t * DIM + d4);
    float4 b = *(const float4*)(pos + (long)s * DIM + d4);
    float4 o;
    o.x = a.x + b.x; o.y = a.y + b.y; o.z = a.z + b.z; o.w = a.w + b.w;
    *(float4*)(g_h + (long)r * DIM + d4) = o;
}

// ---------------- generic tf32 GEMM body, 2-stage pipelined ------------------
// C[m,n] = sum_k A[m,k] * B(k,n) (+ bias[n])
// BMODE 0: B stored [K,N] row-major    BMODE 1: B stored [N,K] row-major (q@k^T)
#define BMT 128
#define BNT 128
#define BKT 32
#define ASTR 36    // BKT+4:  A-frag addr mod 32 = 4*grp + t4 -> conflict-free
#define BSTR 136   // BNT+8:  B-frag addr mod 32 = 8*t4 + grp -> conflict-free
#define AWORDS (BMT*ASTR)
#define BWORDS (BKT*BSTR)
#define SMEM_BYTES ((2*AWORDS + 2*BWORDS) * 4)

template<int BMODE>
__device__ __forceinline__
void gemm_body(const float* __restrict__ A, const float* __restrict__ B,
               const float* __restrict__ bias, float* __restrict__ C,
               int N, int K, int rm, int cn, int kend, int streaming,
               uint32_t* smem)
{
    uint32_t* Ash = smem;                 // [2][AWORDS]
    uint32_t* Bsh = smem + 2 * AWORDS;    // [2][BWORDS]

    const int tid  = threadIdx.x;
    const int lane = tid & 31;
    const int warp = tid >> 5;
    const int grp  = lane >> 2;
    const int t4   = lane & 3;
    const int wm   = (warp >> 1) * 32;   // 4 warps along M
    const int wn   = (warp & 1) * 64;    // 2 warps along N

    // staging indices
    const int arow = tid >> 3;           // 0..31
    const int ac4  = (tid & 7) * 4;      // 0..28
    const int bk   = tid >> 5;           // 0..7   (BMODE 0)
    const int bn4  = (tid & 31) * 4;     // 0..124 (BMODE 0)

    float acc[2][8][4] = {};
    float4 ra[4], rb[4];

    auto ldg_tile = [&](int k0) {
        #pragma unroll
        for (int p = 0; p < 4; p++)
            ra[p] = *(const float4*)(A + (long)(rm + p * 32 + arow) * K + k0 + ac4);
        if (BMODE == 0) {
            #pragma unroll
            for (int p = 0; p < 4; p++)
                rb[p] = *(const float4*)(B + (long)(k0 + p * 8 + bk) * N + cn + bn4);
        } else {
            #pragma unroll
            for (int p = 0; p < 4; p++)
                rb[p] = *(const float4*)(B + (long)(cn + p * 32 + arow) * K + k0 + ac4);
        }
    };

    auto sts_tile = [&](int buf) {
        uint32_t* As = Ash + buf * AWORDS;
        uint32_t* Bs = Bsh + buf * BWORDS;
        #pragma unroll
        for (int p = 0; p < 4; p++) {
            uint4 u;
            u.x = f2tf(ra[p].x); u.y = f2tf(ra[p].y);
            u.z = f2tf(ra[p].z); u.w = f2tf(ra[p].w);
            *(uint4*)(As + (p * 32 + arow) * ASTR + ac4) = u;
        }
        if (BMODE == 0) {
            #pragma unroll
            for (int p = 0; p < 4; p++) {
                uint4 u;
                u.x = f2tf(rb[p].x); u.y = f2tf(rb[p].y);
                u.z = f2tf(rb[p].z); u.w = f2tf(rb[p].w);
                *(uint4*)(Bs + (p * 8 + bk) * BSTR + bn4) = u;
            }
        } else {
            #pragma unroll
            for (int p = 0; p < 4; p++) {
                int n = p * 32 + arow;
                Bs[(ac4 + 0) * BSTR + n] = f2tf(rb[p].x);
                Bs[(ac4 + 1) * BSTR + n] = f2tf(rb[p].y);
                Bs[(ac4 + 2) * BSTR + n] = f2tf(rb[p].z);
                Bs[(ac4 + 3) * BSTR + n] = f2tf(rb[p].w);
            }
        }
    };

    // compute k-steps [ks0, ks1) of the 4 in a tile
    auto compute = [&](int buf, int ks0, int ks1) {
        const uint32_t* As = Ash + buf * AWORDS;
        const uint32_t* Bs = Bsh + buf * BWORDS;
        #pragma unroll
        for (int ks = ks0; ks < ks1; ks++) {
            const int kk = ks * 8;
            uint32_t a[2][4];
            #pragma unroll
            for (int mt = 0; mt < 2; mt++) {
                int r = wm + mt * 16;
                a[mt][0] = As[(r + grp    ) * ASTR + kk + t4    ];
                a[mt][1] = As[(r + grp + 8) * ASTR + kk + t4    ];
                a[mt][2] = As[(r + grp    ) * ASTR + kk + t4 + 4];
                a[mt][3] = As[(r + grp + 8) * ASTR + kk + t4 + 4];
            }
            #pragma unroll
            for (int nt = 0; nt < 8; nt++) {
                uint32_t b[2];
                int c = wn + nt * 8 + grp;
                b[0] = Bs[(kk + t4    ) * BSTR + c];
                b[1] = Bs[(kk + t4 + 4) * BSTR + c];
                mma8(acc[0][nt], a[0], b);
                mma8(acc[1][nt], a[1], b);
            }
        }
    };

    // ---- 2-stage pipeline, split compute around STS to bound reg pressure:
    //      ldg(next) | compute(cur, 0..2) | sts(next) | compute(cur, 2..4) | bar
    const int nIter = kend / BKT;
    ldg_tile(0);
    sts_tile(0);
    __syncthreads();
    for (int it = 0; it < nIter; ++it) {
        const bool more = (it + 1 < nIter);
        if (more) ldg_tile((it + 1) * BKT);
        compute(it & 1, 0, 2);
        if (more) sts_tile((it + 1) & 1);
        compute(it & 1, 2, 4);
        if (more) __syncthreads();
    }

    // -- epilogue: paired float2 stores; streaming (evict-first) optional
    #pragma unroll
    for (int mt = 0; mt < 2; mt++) {
        #pragma unroll
        for (int nt = 0; nt < 8; nt++) {
            int r0 = rm + wm + mt * 16 + grp;
            int c0 = cn + wn + nt * 8 + t4 * 2;
            float b0 = bias ? bias[c0]     : 0.f;
            float b1 = bias ? bias[c0 + 1] : 0.f;
            float2 lo = make_float2(acc[mt][nt][0] + b0, acc[mt][nt][1] + b1);
            float2 hi = make_float2(acc[mt][nt][2] + b0, acc[mt][nt][3] + b1);
            float2* p0 = (float2*)(C + (long)r0 * N + c0);
            float2* p1 = (float2*)(C + (long)(r0 + 8) * N + c0);
            if (streaming) { __stcs(p0, lo); __stcs(p1, hi); }
            else           { *p0 = lo;       *p1 = hi;       }
        }
    }
}

// ---------------- generic wrapper --------------------------------------------
// cmode 0: plain  1: causal scores (skip fully-masked blocks)
// cmode 2: causal A@V (clip K-loop at rm+BMT; attn is exactly 0 beyond row)
// cmode 3: plain, SWAPPED grid (blockIdx.x -> M) + STREAMING C stores
// cmodes 1,2 use LPT ordering: heavy (large-rm) row-blocks dispatch FIRST so
// the work-stealing scheduler backfills the light/early-return blocks.
template<int BMODE>
__global__ __launch_bounds__(256, 2)
void gemm_kernel(const float* __restrict__ A, const float* __restrict__ B,
                 const float* __restrict__ bias, float* __restrict__ C,
                 int M, int N, int K,
                 long sA, long sB, long sC, int cmode)
{
    extern __shared__ uint32_t smem[];
    const int bz = blockIdx.z;
    A += (long)bz * sA;  B += (long)bz * sB;  C += (long)bz * sC;

    int rm, cn;
    if (cmode == 3)      { rm = blockIdx.x * BMT; cn = blockIdx.y * BNT; }
    else if (cmode >= 1) { rm = (gridDim.y - 1 - blockIdx.y) * BMT;       // LPT
                           cn = blockIdx.x * BNT; }
    else                 { rm = blockIdx.y * BMT; cn = blockIdx.x * BNT; }

    if (cmode == 1 && cn > rm + (BMT - 1)) return;   // fully masked: never touched
    int kend = K;
    if (cmode == 2) { int ke = rm + BMT; kend = (ke < K) ? ke : K; }

    gemm_body<BMODE>(A, B, bias, C, N, K, rm, cn, kend, cmode == 3, smem);
}

// ---------------- fused QKV wrapper: blockIdx.z selects q/k/v ----------------
struct QKVPtrs {
    const float* B[3];
    const float* bias[3];
    float*       C[3];
};

__global__ __launch_bounds__(256, 2)
void qkv_kernel(const float* __restrict__ A, QKVPtrs p)
{
    extern __shared__ uint32_t smem[];
    const int z  = blockIdx.z;          // 0:q 1:k 2:v
    const int rm = blockIdx.y * BMT;
    const int cn = blockIdx.x * BNT;
    gemm_body<0>(A, p.B[z], p.bias[z], p.C[z], DIM, DIM, rm, cn, DIM, 0, smem);
}

// ---------------- causal softmax over rows of g_sc ---------------------------
// Only reads j <= row (this IS the causal mask); writes zeros above diagonal.
// Vectorized: 2 float4 per thread (2048 = 256 threads * 2 * 4). __expf is
// hardware EX2-based; arg <= 0 so rel err ~1e-6, well under the 1e-3 budget.
__global__ void softmax_kernel() {
    __shared__ float red[8];
    const int row = blockIdx.x;              // 0..4095
    const int b  = row >> 11;
    const int rr = row & (SEQ - 1);
    float* p = g_sc + ((size_t)b << 22) + ((size_t)rr << 11);
    const int tid = threadIdx.x;

    // load 2 float4 chunks: elements [tid*4 .. tid*4+3] and [1024+tid*4 ..]
    float4 v0 = *(const float4*)(p + tid * 4);
    float4 v1 = *(const float4*)(p + 1024 + tid * 4);
    float ev[8] = { v0.x, v0.y, v0.z, v0.w, v1.x, v1.y, v1.z, v1.w };

    float m = -1e30f;
    #pragma unroll
    for (int i = 0; i < 8; i++) {
        int j = (i < 4) ? tid * 4 + i : 1024 + tid * 4 + (i - 4);
        if (j > rr) ev[i] = -1e30f;
        m = fmaxf(m, ev[i]);
    }
    #pragma unroll
    for (int o = 16; o; o >>= 1) m = fmaxf(m, __shfl_xor_sync(0xffffffffu, m, o));
    if ((tid & 31) == 0) red[tid >> 5] = m;
    __syncthreads();
    float mx = red[0];
    #pragma unroll
    for (int i = 1; i < 8; i++) mx = fmaxf(mx, red[i]);
    __syncthreads();

    float s = 0.f;
    #pragma unroll
    for (int i = 0; i < 8; i++) {
        float e = (ev[i] > -1e29f) ? __expf(ev[i] - mx) : 0.f;
        ev[i] = e;
        s += e;
    }
    #pragma unroll
    for (int o = 16; o; o >>= 1) s += __shfl_xor_sync(0xffffffffu, s, o);
    if ((tid & 31) == 0) red[tid >> 5] = s;
    __syncthreads();
    float tot = 0.f;
    #pragma unroll
    for (int i = 0; i < 8; i++) tot += red[i];
    const float inv = 1.f / tot;

    float4 o0 = make_float4(ev[0]*inv, ev[1]*inv, ev[2]*inv, ev[3]*inv);
    float4 o1 = make_float4(ev[4]*inv, ev[5]*inv, ev[6]*inv, ev[7]*inv);
    *(float4*)(p + tid * 4)        = o0;
    *(float4*)(p + 1024 + tid * 4) = o1;
}

// ---------------- launch -----------------------------------------------------
extern "C" void kernel_launch(void* const* d_in, const int* in_sizes, int n_in,
                              void* d_out, int out_size)
{
    const int*   x   = (const int*)  d_in[0];
    const float* tok = (const float*)d_in[1];
    const float* pos = (const float*)d_in[2];
    const float* wq  = (const float*)d_in[3];
    const float* bq  = (const float*)d_in[4];
    const float* wk  = (const float*)d_in[5];
    const float* bk  = (const float*)d_in[6];
    const float* wv  = (const float*)d_in[7];
    const float* bv  = (const float*)d_in[8];
    const float* wo  = (const float*)d_in[9];
    const float* bo  = (const float*)d_in[10];
    float* out = (float*)d_out;

    float *h, *q, *k, *v, *sc, *ao;
    cudaGetSymbolAddress((void**)&h,  g_h);
    cudaGetSymbolAddress((void**)&q,  g_q);
    cudaGetSymbolAddress((void**)&k,  g_k);
    cudaGetSymbolAddress((void**)&v,  g_v);
    cudaGetSymbolAddress((void**)&sc, g_sc);
    cudaGetSymbolAddress((void**)&ao, g_ao);

    // opt-in to >48KB dynamic smem (host-side attribute set; capture-safe,
    // called unconditionally -> deterministic)
    cudaFuncSetAttribute(gemm_kernel<0>, cudaFuncAttributeMaxDynamicSharedMemorySize, SMEM_BYTES);
    cudaFuncSetAttribute(gemm_kernel<1>, cudaFuncAttributeMaxDynamicSharedMemorySize, SMEM_BYTES);
    cudaFuncSetAttribute(qkv_kernel,     cudaFuncAttributeMaxDynamicSharedMemorySize, SMEM_BYTES);

    // h = tok_emb[x] + pos_emb
    embed_kernel<<<MTOT, 256>>>(x, tok, pos);

    // fused q,k,v projections: one launch, gridDim.z selects weight/bias/out
    QKVPtrs p;
    p.B[0] = wq; p.B[1] = wk; p.B[2] = wv;
    p.bias[0] = bq; p.bias[1] = bk; p.bias[2] = bv;
    p.C[0] = q; p.C[1] = k; p.C[2] = v;
    qkv_kernel<<<dim3(DIM / BNT, MTOT / BMT, 3), 256, SMEM_BYTES>>>(h, p);

    // scores = q @ k^T per batch (skip fully-masked upper blocks; LPT order)
    gemm_kernel<1><<<dim3(SEQ / BNT, SEQ / BMT, NBATCH), 256, SMEM_BYTES>>>(
        q, k, nullptr, sc, SEQ, SEQ, DIM,
        (long)SEQ * DIM, (long)SEQ * DIM, (long)SEQ * SEQ, 1);

    // causal softmax (in place)
    softmax_kernel<<<MTOT, 256>>>();

    // out = attn @ v per batch (K-loop clipped by causality; LPT order)
    gemm_kernel<0><<<dim3(DIM / BNT, SEQ / BMT, NBATCH), 256, SMEM_BYTES>>>(
        sc, v, nullptr, ao, SEQ, DIM, SEQ,
        (long)SEQ * SEQ, (long)SEQ * DIM, (long)SEQ * DIM, 2);

    // logits = out @ wo + bo : [4096,1024] x [1024,32000]
    // SWAPPED grid + streaming C stores (cmode 3): wo column-groups hit DRAM
    // once and are L2-shared across all 32 M-blocks; logits bypass L2.
    gemm_kernel<0><<<dim3(MTOT / BMT, VOCAB / BNT, 1), 256, SMEM_BYTES>>>(
        ao, wo, bo, out, MTOT, VOCAB, DIM, 0, 0, 0, 3);
}